// round 5
// baseline (speedup 1.0000x reference)
#include <cuda_runtime.h>
#include <math.h>

#define NUM_CLASSES 10000
#define FEATURE_DIM 512

// Scratch (__device__ globals: zero-initialized at module load; every kernel
// execution restores them to zero, keeping replays deterministic).
__device__ float        g_dsum[NUM_CLASSES];
__device__ int          g_count[NUM_CLASSES];
__device__ unsigned int g_ticket;

// ---------------------------------------------------------------------------
// Single fused kernel.
// Phase 1: one warp per sample. dist = ||feat_i - centers[label_i]||.
//          lane 0 does spread-address atomics: dsum[lbl] += dist, count[lbl]++.
// Phase 2: last block to finish reduces sum_c dsum[c]/count[c], writes the
//          scalar output, and re-zeroes all scratch.
// ---------------------------------------------------------------------------
__global__ void __launch_bounds__(256) centerloss_kernel(
    const float* __restrict__ feat,
    const int*   __restrict__ label,
    const float* __restrict__ centers,
    float*       __restrict__ out,
    int batch, float inv_batch)
{
    const int warp_global = (blockIdx.x * blockDim.x + threadIdx.x) >> 5;
    const int lane        = threadIdx.x & 31;

    // ---------------- Phase 1: per-sample distance ----------------
    if (warp_global < batch) {
        const int lbl = label[warp_global];

        const float4* __restrict__ f =
            reinterpret_cast<const float4*>(feat + (size_t)warp_global * FEATURE_DIM);
        const float4* __restrict__ c =
            reinterpret_cast<const float4*>(centers + (size_t)lbl * FEATURE_DIM);

        float acc = 0.0f;
        #pragma unroll
        for (int j = 0; j < FEATURE_DIM / 4 / 32; j++) {   // 4 iterations
            float4 a = __ldcs(&f[lane + j * 32]);   // streamed: no reuse
            float4 b = __ldg (&c[lane + j * 32]);   // cached: 1.64x avg reuse
            float dx = a.x - b.x;
            float dy = a.y - b.y;
            float dz = a.z - b.z;
            float dw = a.w - b.w;
            acc = fmaf(dx, dx, acc);
            acc = fmaf(dy, dy, acc);
            acc = fmaf(dz, dz, acc);
            acc = fmaf(dw, dw, acc);
        }

        #pragma unroll
        for (int o = 16; o > 0; o >>= 1)
            acc += __shfl_xor_sync(0xffffffffu, acc, o);

        if (lane == 0) {
            atomicAdd(&g_dsum[lbl], sqrtf(acc));   // spread-address REDG
            atomicAdd(&g_count[lbl], 1);
        }
    }

    // ---------------- Phase 2: last block reduces classes ----------------
    __shared__ bool  s_is_last;
    __shared__ float s_part[8];

    __syncthreads();
    __threadfence();   // make this block's atomics visible before ticket
    if (threadIdx.x == 0) {
        unsigned t = atomicAdd(&g_ticket, 1u);
        s_is_last = (t == gridDim.x - 1);
    }
    __syncthreads();

    if (s_is_last) {
        // All other blocks' atomics are ordered before their ticket increments;
        // reading after observing the final ticket value is safe (read via
        // L2-coherent __ldcg).
        float partial = 0.0f;
        for (int cIdx = threadIdx.x; cIdx < NUM_CLASSES; cIdx += blockDim.x) {
            int   cnt = __ldcg(&g_count[cIdx]);
            float ds  = __ldcg(&g_dsum[cIdx]);
            g_count[cIdx] = 0;       // restore invariant for next replay
            g_dsum[cIdx]  = 0.0f;
            if (cnt > 0) partial += ds / (float)cnt;
        }

        // block reduction (256 threads = 8 warps)
        #pragma unroll
        for (int o = 16; o > 0; o >>= 1)
            partial += __shfl_xor_sync(0xffffffffu, partial, o);
        if (lane == 0) s_part[threadIdx.x >> 5] = partial;
        __syncthreads();
        if (threadIdx.x == 0) {
            float total = 0.0f;
            #pragma unroll
            for (int k = 0; k < 8; k++) total += s_part[k];
            out[0]   = total * inv_batch;
            g_ticket = 0;            // restore invariant
        }
    }
}

// ---------------------------------------------------------------------------
// launch: ONE kernel node in the graph.
// ---------------------------------------------------------------------------
extern "C" void kernel_launch(void* const* d_in, const int* in_sizes, int n_in,
                              void* d_out, int out_size)
{
    const float* feat    = (const float*)d_in[0];
    const int*   label   = (const int*)d_in[1];
    const float* centers = (const float*)d_in[2];
    float*       out     = (float*)d_out;

    const int batch = in_sizes[1];                       // 16384

    const int threads = 256;                              // 8 warps = 8 samples/block... (16 samples: 8 warps, 1 sample/warp)
    const int warps_per_block = threads / 32;
    const int blocks = (batch + warps_per_block - 1) / warps_per_block;

    centerloss_kernel<<<blocks, threads>>>(feat, label, centers, out,
                                           batch, 1.0f / (float)batch);
}

// round 6
// speedup vs baseline: 1.6667x; 1.6667x over previous
#include <cuda_runtime.h>
#include <math.h>

#define NUM_CLASSES 10000
#define FEATURE_DIM 512

// Scratch (__device__ globals). Zero at module load (.bss); K2 re-zeroes them
// every execution, so each graph replay starts from the same state.
__device__ float g_dsum[NUM_CLASSES];
__device__ int   g_count[NUM_CLASSES];

// ---------------------------------------------------------------------------
// K1: one warp per sample. dist = ||feat_i - centers[label_i]||.
// lane 0: spread-address atomics  dsum[lbl] += dist, count[lbl] += 1.
// No fence, no ticket — the kernel boundary orders K1's atomics before K2.
// ---------------------------------------------------------------------------
__global__ void __launch_bounds__(256) dist_kernel(
    const float* __restrict__ feat,
    const int*   __restrict__ label,
    const float* __restrict__ centers,
    int batch)
{
    const int warp_global = (blockIdx.x * blockDim.x + threadIdx.x) >> 5;
    const int lane        = threadIdx.x & 31;

    if (warp_global >= batch) return;

    const int lbl = label[warp_global];

    const float4* __restrict__ f =
        reinterpret_cast<const float4*>(feat + (size_t)warp_global * FEATURE_DIM);
    const float4* __restrict__ c =
        reinterpret_cast<const float4*>(centers + (size_t)lbl * FEATURE_DIM);

    float acc = 0.0f;
    #pragma unroll
    for (int j = 0; j < FEATURE_DIM / 4 / 32; j++) {   // 4 iters, 8 LDG.128 batched
        float4 a = f[lane + j * 32];                   // feat: streamed once
        float4 b = __ldg(&c[lane + j * 32]);           // centers: L2 reuse
        float dx = a.x - b.x;
        float dy = a.y - b.y;
        float dz = a.z - b.z;
        float dw = a.w - b.w;
        acc = fmaf(dx, dx, acc);
        acc = fmaf(dy, dy, acc);
        acc = fmaf(dz, dz, acc);
        acc = fmaf(dw, dw, acc);
    }

    #pragma unroll
    for (int o = 16; o > 0; o >>= 1)
        acc += __shfl_xor_sync(0xffffffffu, acc, o);

    if (lane == 0) {
        atomicAdd(&g_dsum[lbl], sqrtf(acc));   // spread-address REDG
        atomicAdd(&g_count[lbl], 1);           // spread-address REDG
    }
}

// ---------------------------------------------------------------------------
// K2: single block, 1024 threads. sum_c dsum[c]/count[c]; re-zero scratch;
// write the scalar. 80 KB of L2-resident reads — independent loads, one
// latency exposure.
// ---------------------------------------------------------------------------
__global__ void __launch_bounds__(1024) reduce_kernel(
    float* __restrict__ out, float inv_batch)
{
    const int tid  = threadIdx.x;
    const int lane = tid & 31;
    const int wid  = tid >> 5;

    float partial = 0.0f;
    #pragma unroll
    for (int c = tid; c < NUM_CLASSES; c += 1024) {    // ~10 iterations
        int   cnt = __ldcg(&g_count[c]);
        float ds  = __ldcg(&g_dsum[c]);
        g_count[c] = 0;                                 // restore invariant
        g_dsum[c]  = 0.0f;
        if (cnt > 0) partial += ds / (float)cnt;
    }

    // reduce 1024 threads: warp shuffle, then cross-warp via shared
    #pragma unroll
    for (int o = 16; o > 0; o >>= 1)
        partial += __shfl_xor_sync(0xffffffffu, partial, o);

    __shared__ float s[32];
    if (lane == 0) s[wid] = partial;
    __syncthreads();

    if (wid == 0) {
        float v = (lane < 32) ? s[lane] : 0.0f;
        #pragma unroll
        for (int o = 16; o > 0; o >>= 1)
            v += __shfl_xor_sync(0xffffffffu, v, o);
        if (lane == 0) out[0] = v * inv_batch;
    }
}

// ---------------------------------------------------------------------------
// launch: TWO kernel nodes in the graph.
// ---------------------------------------------------------------------------
extern "C" void kernel_launch(void* const* d_in, const int* in_sizes, int n_in,
                              void* d_out, int out_size)
{
    const float* feat    = (const float*)d_in[0];
    const int*   label   = (const int*)d_in[1];
    const float* centers = (const float*)d_in[2];
    float*       out     = (float*)d_out;

    const int batch = in_sizes[1];                       // 16384

    const int threads = 256;                             // 8 warps, 1 sample/warp
    const int warps_per_block = threads / 32;
    const int blocks = (batch + warps_per_block - 1) / warps_per_block;

    dist_kernel<<<blocks, threads>>>(feat, label, centers, batch);
    reduce_kernel<<<1, 1024>>>(out, 1.0f / (float)batch);
}

// round 10
// speedup vs baseline: 2.1007x; 1.2604x over previous
#include <cuda_runtime.h>
#include <math.h>

#define NUM_CLASSES 10000
#define FEATURE_DIM 512

// Scratch (__device__ globals). Zero at module load (.bss); K2 restores all of
// them to zero every execution, so each graph replay starts identically.
__device__ float        g_dsum[NUM_CLASSES];
__device__ int          g_count[NUM_CLASSES];
__device__ float        g_loss;
__device__ unsigned int g_ticket;

// ---------------------------------------------------------------------------
// K1: one warp per sample. dist = ||feat_i - centers[label_i]||.
// lane 0: spread-address REDG atomics  dsum[lbl] += dist, count[lbl] += 1.
// Kernel boundary (graph edge) orders these before K2 — no fence needed here.
// ---------------------------------------------------------------------------
__global__ void __launch_bounds__(256) dist_kernel(
    const float* __restrict__ feat,
    const int*   __restrict__ label,
    const float* __restrict__ centers,
    int batch)
{
    const int warp_global = (blockIdx.x * blockDim.x + threadIdx.x) >> 5;
    const int lane        = threadIdx.x & 31;

    if (warp_global >= batch) return;

    const int lbl = label[warp_global];   // broadcast load across the warp

    const float4* __restrict__ f =
        reinterpret_cast<const float4*>(feat + (size_t)warp_global * FEATURE_DIM);
    const float4* __restrict__ c =
        reinterpret_cast<const float4*>(centers + (size_t)lbl * FEATURE_DIM);

    float acc = 0.0f;
    #pragma unroll
    for (int j = 0; j < FEATURE_DIM / 4 / 32; j++) {   // 4 iters → 8 LDG.128 in flight
        float4 a = f[lane + j * 32];                   // feat: streamed once
        float4 b = __ldg(&c[lane + j * 32]);           // centers: L2 reuse
        float dx = a.x - b.x;
        float dy = a.y - b.y;
        float dz = a.z - b.z;
        float dw = a.w - b.w;
        acc = fmaf(dx, dx, acc);
        acc = fmaf(dy, dy, acc);
        acc = fmaf(dz, dz, acc);
        acc = fmaf(dw, dw, acc);
    }

    #pragma unroll
    for (int o = 16; o > 0; o >>= 1)
        acc += __shfl_xor_sync(0xffffffffu, acc, o);

    if (lane == 0) {
        atomicAdd(&g_dsum[lbl], sqrtf(acc));
        atomicAdd(&g_count[lbl], 1);
    }
}

// ---------------------------------------------------------------------------
// K2: class reduction spread over many SMs (fixes R5's single-SM LSU floor).
// One class per thread; block partial -> REDG atomicAdd into g_loss.
// Last-block ticket (only ~79 arrivals: cheap) writes the scalar output and
// re-zeroes g_loss / g_ticket. Each thread re-zeroes its own class slots.
// ---------------------------------------------------------------------------
#define K2_THREADS 128
#define K2_BLOCKS  ((NUM_CLASSES + K2_THREADS - 1) / K2_THREADS)   // 79

__global__ void __launch_bounds__(K2_THREADS) classreduce_kernel(
    float* __restrict__ out, float inv_batch)
{
    const int tid  = blockIdx.x * K2_THREADS + threadIdx.x;
    const int lane = threadIdx.x & 31;
    const int wid  = threadIdx.x >> 5;

    float partial = 0.0f;
    if (tid < NUM_CLASSES) {
        int   cnt = __ldcg(&g_count[tid]);
        float ds  = __ldcg(&g_dsum[tid]);
        g_count[tid] = 0;          // restore replay invariant
        g_dsum[tid]  = 0.0f;
        if (cnt > 0) partial = ds / (float)cnt;
    }

    // block reduction: 4 warps
    #pragma unroll
    for (int o = 16; o > 0; o >>= 1)
        partial += __shfl_xor_sync(0xffffffffu, partial, o);

    __shared__ float s[4];
    __shared__ bool  s_last;
    if (lane == 0) s[wid] = partial;
    __syncthreads();

    if (threadIdx.x == 0) {
        float bsum = s[0] + s[1] + s[2] + s[3];
        atomicAdd(&g_loss, bsum);
        __threadfence();                                   // order g_loss add before ticket
        unsigned t = atomicAdd(&g_ticket, 1u);
        s_last = (t == gridDim.x - 1);
    }
    __syncthreads();

    if (s_last && threadIdx.x == 0) {
        // all blocks' g_loss adds are fenced before their ticket increments
        out[0]   = __ldcg(&g_loss) * inv_batch;
        g_loss   = 0.0f;                                   // restore invariants
        g_ticket = 0u;
    }
}

// ---------------------------------------------------------------------------
// launch: TWO kernel nodes in the graph.
// ---------------------------------------------------------------------------
extern "C" void kernel_launch(void* const* d_in, const int* in_sizes, int n_in,
                              void* d_out, int out_size)
{
    const float* feat    = (const float*)d_in[0];
    const int*   label   = (const int*)d_in[1];
    const float* centers = (const float*)d_in[2];
    float*       out     = (float*)d_out;

    const int batch = in_sizes[1];                        // 16384

    const int threads = 256;                              // 8 warps, 1 sample/warp
    const int warps_per_block = threads / 32;
    const int blocks = (batch + warps_per_block - 1) / warps_per_block;

    dist_kernel<<<blocks, threads>>>(feat, label, centers, batch);
    classreduce_kernel<<<K2_BLOCKS, K2_THREADS>>>(out, 1.0f / (float)batch);
}